// round 17
// baseline (speedup 1.0000x reference)
#include <cuda_runtime.h>
#include <cuda_fp16.h>

#define MDIM   1024
#define NITEMS 2048             // split schedule: plus(i) and prod(i) independent
#define GR     32               // rows per block = 16 warps x 2 rows (half2-packed)
#define TPB    512
#define PAIRSTRIDE (3*MDIM)     // half2 words per pair: [x(1024) | items(2048)]

typedef unsigned int u32;

// persistent shared layout
#define BUF_BYTES  (16*PAIRSTRIDE*4)           // 196608
#define REC_OFF    (BUF_BYTES)                 // uint2[2048] (e0|e1|flag, w0|w1) 16384
#define BT_OFF     (REC_OFF  + NITEMS*8)       // half[2048] b'                   4096
#define WEPIF_OFF  (BT_OFF   + NITEMS*2)       // float[2048] epilogue w permuted 8192
#define OFFS_OFF   (WEPIF_OFF+ NITEMS*4)       // short[2052] level offsets       4104
#define SMEM_BYTES (OFFS_OFF + 4104)           // 229384 <= 232448 cap

__device__ __forceinline__ __half2 tanh2_approx(__half2 v) {
    u32 u = *reinterpret_cast<u32*>(&v);
    u32 r;
    asm("tanh.approx.f16x2 %0, %1;" : "=r"(r) : "r"(u));
    return *reinterpret_cast<__half2*>(&r);
}

// ---------------------------------------------------------------------------
// Split-item schedule: 2048 items (item j<1024 = plus(j), j>=1024 = prod).
// Each item has 2 parents -> true dataflow depth (~half the merged depth).
// Unified body: gather a0,a1; compute sigmoid(hfma2+tanh) AND product(hmul2);
// select by flag bit; one contiguous STS.32. Value space in half2 words:
//   x -> c in [0,1024); item j -> 1024 + pos[j].
// 16 warps x 2 rows/warp (half2), block-local schedule, 2 group-waves.
// ---------------------------------------------------------------------------
__global__ void __launch_bounds__(TPB, 1)
tree_kernel(const float* __restrict__ x,      const int* __restrict__ raw,
            const float* __restrict__ W_base, const float* __restrict__ b_base,
            const float* __restrict__ W_sig,  const float* __restrict__ b_sig,
            const float* __restrict__ w_plus, const float* __restrict__ b_plus,
            const float* __restrict__ w_prod, const float* __restrict__ b_prod,
            float* __restrict__ out, int nGroups)
{
    extern __shared__ char smraw[];
    __half2* buf   = (__half2*)smraw;                    // [16][PAIRSTRIDE]
    uint2*   sRec  = (uint2*) (smraw + REC_OFF);
    __half*  sBt   = (__half*)(smraw + BT_OFF);
    float*   wepiF = (float*) (smraw + WEPIF_OFF);
    short*   offs  = (short*) (smraw + OFFS_OFF);

    // setup scratch overlaid on buf (released before staging rows)
    int* lvl  = (int*)(smraw);                           // [2048]
    int* cnt  = (int*)(smraw + 8192);                    // [2048]
    int* cur  = (int*)(smraw + 16384);                   // [2048]
    int* posA = (int*)(smraw + 24576);                   // [2048]

    int tid  = threadIdx.x;
    int lane = tid & 31;
    int wid  = tid >> 5;

    // ---- Phase 0: zero counters -------------------------------------------
    for (int j = tid; j < NITEMS; j += TPB) cnt[j] = 0;
    __syncthreads();

    // ---- Phase 1: exact item levels, warp 0 over 32-step chunks -----------
    // lane holds (lp, lq) = levels of plus(i) and prod(i) for its step.
    if (wid == 0) {
        for (int c = 0; c < MDIM/32; c++) {
            int i = c*32 + lane, base = c*32;
            int q0 = raw[2*i],            q1 = raw[2*i + 1];
            int q2 = raw[2*MDIM + 2*i],   q3 = raw[2*MDIM + 2*i + 1];
            int lp = 0, lq = 0;
            int e0 = -1, e1 = -1, e2 = -1, e3 = -1;
            int t0 = 0,  t1 = 0,  t2 = 0,  t3 = 0;       // parent-is-prod
            if (q0 >= MDIM) { int s = q0 & 1023; int ip = (q0 >= 2*MDIM);
                if (s < base) lp = max(lp, lvl[s + (ip ? 1024 : 0)] + 1);
                else { e0 = s - base; t0 = ip; } }
            if (q1 >= MDIM) { int s = q1 & 1023; int ip = (q1 >= 2*MDIM);
                if (s < base) lp = max(lp, lvl[s + (ip ? 1024 : 0)] + 1);
                else { e1 = s - base; t1 = ip; } }
            if (q2 >= MDIM) { int s = q2 & 1023; int ip = (q2 >= 2*MDIM);
                if (s < base) lq = max(lq, lvl[s + (ip ? 1024 : 0)] + 1);
                else { e2 = s - base; t2 = ip; } }
            if (q3 >= MDIM) { int s = q3 & 1023; int ip = (q3 >= 2*MDIM);
                if (s < base) lq = max(lq, lvl[s + (ip ? 1024 : 0)] + 1);
                else { e3 = s - base; t3 = ip; } }
            for (;;) {
                int vp0 = __shfl_sync(0xffffffffu, lp, e0 < 0 ? 0 : e0);
                int vq0 = __shfl_sync(0xffffffffu, lq, e0 < 0 ? 0 : e0);
                int vp1 = __shfl_sync(0xffffffffu, lp, e1 < 0 ? 0 : e1);
                int vq1 = __shfl_sync(0xffffffffu, lq, e1 < 0 ? 0 : e1);
                int vp2 = __shfl_sync(0xffffffffu, lp, e2 < 0 ? 0 : e2);
                int vq2 = __shfl_sync(0xffffffffu, lq, e2 < 0 ? 0 : e2);
                int vp3 = __shfl_sync(0xffffffffu, lp, e3 < 0 ? 0 : e3);
                int vq3 = __shfl_sync(0xffffffffu, lq, e3 < 0 ? 0 : e3);
                int nlp = lp, nlq = lq;
                if (e0 >= 0) nlp = max(nlp, (t0 ? vq0 : vp0) + 1);
                if (e1 >= 0) nlp = max(nlp, (t1 ? vq1 : vp1) + 1);
                if (e2 >= 0) nlq = max(nlq, (t2 ? vq2 : vp2) + 1);
                if (e3 >= 0) nlq = max(nlq, (t3 ? vq3 : vp3) + 1);
                unsigned ch = __ballot_sync(0xffffffffu, (nlp != lp) || (nlq != lq));
                lp = nlp; lq = nlq;
                if (!ch) break;
            }
            lvl[i] = lp; lvl[1024 + i] = lq;
        }
    }
    __syncthreads();

    // ---- Phase 2: level histogram over 2048 items -------------------------
    for (int j = tid; j < NITEMS; j += TPB) atomicAdd(&cnt[lvl[j]], 1);
    __syncthreads();

    // ---- Phase 3: warp-0 scan -> level offsets ----------------------------
    if (wid == 0) {
        int carry = 0;
        for (int b = 0; b < NITEMS; b += 32) {
            int v = cnt[b + lane];
            int s = v;
            #pragma unroll
            for (int o = 1; o < 32; o <<= 1) {
                int t = __shfl_up_sync(0xffffffffu, s, o);
                if (lane >= o) s += t;
            }
            int excl = carry + s - v;
            offs[b + lane] = (short)excl;
            cur[b + lane]  = excl;
            carry += __shfl_sync(0xffffffffu, s, 31);
        }
        if (lane == 0) { offs[NITEMS] = NITEMS; offs[NITEMS+1] = NITEMS; }
    }
    __syncthreads();

    // ---- Phase 4: schedule position of every item -------------------------
    for (int j = tid; j < NITEMS; j += TPB) posA[j] = atomicAdd(&cur[lvl[j]], 1);
    __syncthreads();

    // ---- Phase 5: emit records --------------------------------------------
    // enc(q): q<M -> q ; plus(s) -> 1024+pos[s] ; prod(s) -> 1024+pos[1024+s]
    for (int j = tid; j < NITEMS; j += TPB) {
        int isProd = (j >= 1024);
        int i = isProd ? (j - 1024) : j;
        int q0 = isProd ? raw[2*MDIM + 2*i] : raw[2*i];
        int q1 = isProd ? raw[2*MDIM + 2*i + 1] : raw[2*i + 1];
        int e0 = (q0 < MDIM) ? q0 : (q0 < 2*MDIM ? 1024 + posA[q0 - MDIM]
                                                 : 1024 + posA[1024 + q0 - 2*MDIM]);
        int e1 = (q1 < MDIM) ? q1 : (q1 < 2*MDIM ? 1024 + posA[q1 - MDIM]
                                                 : 1024 + posA[1024 + q1 - 2*MDIM]);
        float w0 = isProd ? 0.f : W_sig[2*i]     * 0.5f;
        float w1 = isProd ? 0.f : W_sig[2*i + 1] * 0.5f;
        float bb = isProd ? 0.f : b_sig[i]       * 0.5f;
        int pos = posA[j];
        __half2 hw = __floats2half2_rn(w0, w1);
        uint2 rec;
        rec.x = (u32)e0 | ((u32)e1 << 16) | ((u32)isProd << 31);
        rec.y = *reinterpret_cast<u32*>(&hw);
        sRec[pos]  = rec;
        sBt[pos]   = __float2half_rn(bb);
        wepiF[pos] = isProd ? w_prod[i] : w_plus[i];
    }
    __syncthreads();                     // last block-wide barrier

    // ---- Main: one warp per ROW-PAIR, persistent over groups --------------
    __half2* pb = buf + wid * PAIRSTRIDE;    // x[0,1024) items[1024,3072)
    float bias = b_base[0] + b_plus[0] + b_prod[0];
    const __half2 H05 = __floats2half2_rn(0.5f, 0.5f);

    for (int grp = blockIdx.x; grp < nGroups; grp += gridDim.x) {
        int rowA = grp * GR + 2*wid;

        // stage both rows (fp32 coalesced), pack half2, fold x.W_base in fp32
        const float4* xrA = (const float4*)(x + (size_t)rowA * MDIM);
        const float4* xrB = (const float4*)(x + (size_t)(rowA + 1) * MDIM);
        const float4* wb4 = (const float4*)W_base;
        float accA = 0.f, accB = 0.f;
        #pragma unroll
        for (int k = 0; k < MDIM/128; k++) {
            float4 a  = xrA[lane + 32*k];
            float4 b  = xrB[lane + 32*k];
            float4 wv = wb4[lane + 32*k];
            __half2 h[4];
            h[0] = __floats2half2_rn(a.x, b.x);
            h[1] = __floats2half2_rn(a.y, b.y);
            h[2] = __floats2half2_rn(a.z, b.z);
            h[3] = __floats2half2_rn(a.w, b.w);
            ((uint4*)pb)[lane + 32*k] = *(const uint4*)h;
            accA = fmaf(a.x, wv.x, fmaf(a.y, wv.y, fmaf(a.z, wv.z, fmaf(a.w, wv.w, accA))));
            accB = fmaf(b.x, wv.x, fmaf(b.y, wv.y, fmaf(b.z, wv.z, fmaf(b.w, wv.w, accB))));
        }
        __syncwarp();

        // level loop over split items: chunk 0 prefetched; additional chunks
        // (levels are wider now) load records directly with intra-level ILP.
        int s0 = 0;
        int s1 = (int)offs[1];
        int ix, iy; u32 flag; __half2 wlo, whi, bx2;
        if (lane < s1) {
            uint2 r = sRec[lane];
            ix = (int)(r.x & 0xFFFFu);
            iy = (int)((r.x >> 16) & 0x7FFFu);
            flag = r.x >> 31;
            __half2 w2 = *reinterpret_cast<__half2*>(&r.y);
            wlo = __low2half2(w2); whi = __high2half2(w2);
            bx2 = __half2half2(sBt[lane]);
        }

        for (int L = 0; s0 < NITEMS; L++) {
            int s2 = (int)offs[L + 2];
            int n = s1 - s0;
            if (lane < n) {                       // chunk 0 (prefetched)
                __half2 a0 = pb[ix], a1 = pb[iy];
                __half2 z  = __hfma2(wlo, a0, __hfma2(whi, a1, bx2));
                __half2 sg = __hfma2(tanh2_approx(z), H05, H05);
                __half2 pr = __hmul2(a0, a1);
                pb[1024 + s0 + lane] = flag ? pr : sg;   // contiguous STS.32
            }
            for (int cb = s0 + 32; cb < s1; cb += 32) {  // wide-level chunks
                int sp = cb + lane;
                if (sp < s1) {
                    uint2 r2 = sRec[sp];
                    int jx = (int)(r2.x & 0xFFFFu);
                    int jy = (int)((r2.x >> 16) & 0x7FFFu);
                    u32 fl2 = r2.x >> 31;
                    __half2 w2 = *reinterpret_cast<__half2*>(&r2.y);
                    __half2 b2 = __half2half2(sBt[sp]);
                    __half2 a0 = pb[jx], a1 = pb[jy];
                    __half2 z  = __hfma2(__low2half2(w2), a0,
                                 __hfma2(__high2half2(w2), a1, b2));
                    __half2 sg = __hfma2(tanh2_approx(z), H05, H05);
                    __half2 pr = __hmul2(a0, a1);
                    pb[1024 + sp] = fl2 ? pr : sg;
                }
            }
            {   // prefetch + unpack next level chunk 0 (pre-sync, off chain)
                int sp = s1 + lane;
                if (sp < s2) {
                    uint2 r = sRec[sp];
                    ix = (int)(r.x & 0xFFFFu);
                    iy = (int)((r.x >> 16) & 0x7FFFu);
                    flag = r.x >> 31;
                    __half2 w2 = *reinterpret_cast<__half2*>(&r.y);
                    wlo = __low2half2(w2); whi = __high2half2(w2);
                    bx2 = __half2half2(sBt[sp]);
                }
            }
            __syncwarp();
            s0 = s1; s1 = s2;
        }

        // epilogue: single permuted item stream x permuted weights
        for (int m = lane; m < NITEMS; m += 32) {
            float2 v = __half22float2(pb[1024 + m]);
            float  w = wepiF[m];
            accA = fmaf(v.x, w, accA);
            accB = fmaf(v.y, w, accB);
        }
        #pragma unroll
        for (int o = 16; o; o >>= 1) {
            accA += __shfl_xor_sync(0xffffffffu, accA, o);
            accB += __shfl_xor_sync(0xffffffffu, accB, o);
        }
        if (lane == 0) {
            out[rowA]     = accA + bias;
            out[rowA + 1] = accB + bias;
        }
        __syncwarp();
    }
}

// ---------------------------------------------------------------------------
extern "C" void kernel_launch(void* const* d_in, const int* in_sizes, int n_in,
                              void* d_out, int out_size) {
    const float* x  = (const float*)d_in[0];
    const int*   ri = (const int*)  d_in[1];
    const float* Wb = (const float*)d_in[2];
    const float* bb = (const float*)d_in[3];
    const float* Ws = (const float*)d_in[4];
    const float* bs = (const float*)d_in[5];
    const float* wp = (const float*)d_in[6];
    const float* bp = (const float*)d_in[7];
    const float* wq = (const float*)d_in[8];
    const float* bq = (const float*)d_in[9];
    float* out = (float*)d_out;

    int B = in_sizes[0] / MDIM;          // 8192
    int nGroups = B / GR;                // 256

    static int sm_count = 0;
    if (sm_count == 0) {
        int dev = 0;
        cudaGetDevice(&dev);
        cudaDeviceGetAttribute(&sm_count, cudaDevAttrMultiProcessorCount, dev);
        if (sm_count <= 0) sm_count = 148;
        cudaFuncSetAttribute(tree_kernel,
                             cudaFuncAttributeMaxDynamicSharedMemorySize, SMEM_BYTES);
    }
    int grid = nGroups < sm_count ? nGroups : sm_count;

    tree_kernel<<<grid, TPB, SMEM_BYTES>>>(x, ri, Wb, bb, Ws, bs, wp, bp, wq, bq,
                                           out, nGroups);
}